// round 14
// baseline (speedup 1.0000x reference)
#include <cuda_runtime.h>
#include <cuda_bf16.h>
#include <math.h>
#include <stdint.h>

#define N_  2048
#define D_  1024
#define U_  2048
#define NB_ 4
#define M_  8192
#define MD_ 1024

// ---------------- scratch (device globals; no allocs allowed) ----------------
__device__ __align__(16) __nv_bfloat16 g_xbf[(size_t)N_ * D_];        // x bf16 [N,D]
__device__ __align__(16) __nv_bfloat16 g_wcb[(size_t)D_ * U_ * NB_];  // w*sig(delay) bf16 [D,8192]
__device__ __align__(16) __nv_bfloat16 g_rwb[(size_t)U_ * M_];        // read_W bf16 [U,M]
__device__ __align__(16) __nv_bfloat16 g_memb[(size_t)M_ * MD_];      // memory bf16 [M,MD]
__device__ __align__(16) __nv_bfloat16 g_blend[(size_t)N_ * U_];      // bf16 [N,U]
__device__ __align__(16) __nv_bfloat16 g_logits[(size_t)N_ * M_];     // bf16 logits; later
                                                                      // reused as 2x fp32 GEMM3 partials
__device__ __align__(16) __nv_bfloat16 g_attnd[(size_t)N_ * M_];      // (attn-1/M) bf16
__device__ float g_cmpart[8 * MD_];                                   // colsum partials
__device__ float g_gate[N_ * NB_];
__device__ float g_cm[U_];
__device__ float g_wts[8];

// ---------------- PTX helpers ----------------
__device__ __forceinline__ uint32_t smem_u32(const void* p) {
    uint32_t a;
    asm("{ .reg .u64 t; cvta.to.shared.u64 t, %1; cvt.u32.u64 %0, t; }" : "=r"(a) : "l"(p));
    return a;
}
__device__ __forceinline__ void cp16(uint32_t s, const void* g) {
    asm volatile("cp.async.cg.shared.global [%0], [%1], 16;" :: "r"(s), "l"(g));
}
__device__ __forceinline__ void cp_commit() { asm volatile("cp.async.commit_group;"); }
template<int NN> __device__ __forceinline__ void cp_wait() {
    asm volatile("cp.async.wait_group %0;" :: "n"(NN));
}
__device__ __forceinline__ void ldsm4(uint32_t& r0, uint32_t& r1, uint32_t& r2, uint32_t& r3,
                                      uint32_t a) {
    asm volatile("ldmatrix.sync.aligned.m8n8.x4.shared.b16 {%0,%1,%2,%3}, [%4];"
                 : "=r"(r0), "=r"(r1), "=r"(r2), "=r"(r3) : "r"(a));
}
__device__ __forceinline__ void ldsm4t(uint32_t& r0, uint32_t& r1, uint32_t& r2, uint32_t& r3,
                                       uint32_t a) {
    asm volatile("ldmatrix.sync.aligned.m8n8.x4.trans.shared.b16 {%0,%1,%2,%3}, [%4];"
                 : "=r"(r0), "=r"(r1), "=r"(r2), "=r"(r3) : "r"(a));
}
__device__ __forceinline__ void mma_bf16(float* c, const uint32_t* a, const uint32_t* b) {
    asm volatile(
        "mma.sync.aligned.m16n8k16.row.col.f32.bf16.bf16.f32 "
        "{%0,%1,%2,%3}, {%4,%5,%6,%7}, {%8,%9}, {%0,%1,%2,%3};"
        : "+f"(c[0]), "+f"(c[1]), "+f"(c[2]), "+f"(c[3])
        : "r"(a[0]), "r"(a[1]), "r"(a[2]), "r"(a[3]), "r"(b[0]), "r"(b[1]));
}
__device__ __forceinline__ float sigmoidf_(float x) { return 1.f / (1.f + expf(-x)); }
__device__ __forceinline__ float tanh_ap(float x) {
    float r;
    asm("tanh.approx.f32 %0, %1;" : "=f"(r) : "f"(x));
    return r;
}

// ---------------- k_misc: gate softmax (+x->bf16) + conn + act weights + colsums ------
__global__ void __launch_bounds__(256) k_misc(
    const float* __restrict__ x, const float* __restrict__ gW, const float* __restrict__ gb,
    const float* __restrict__ na, const float* __restrict__ W1, const float* __restrict__ b1,
    const float* __restrict__ W2, const float* __restrict__ b2, const float* __restrict__ mask,
    const float* __restrict__ aw, const float* __restrict__ mem) {
    __shared__ float4 sh4[256];
    __shared__ float red[256];
    __shared__ float h32[32];
    int bid = blockIdx.x, t = threadIdx.x;
    if (bid < N_) {
        float4 s = make_float4(0.f, 0.f, 0.f, 0.f);
        #pragma unroll
        for (int i = 0; i < 4; i++) {
            int d = t + i * 256;
            float xv = x[bid * D_ + d];
            g_xbf[(size_t)bid * D_ + d] = __float2bfloat16(xv);   // fused x -> bf16
            float4 g = *(const float4*)&gW[d * 4];
            s.x += xv * g.x; s.y += xv * g.y; s.z += xv * g.z; s.w += xv * g.w;
        }
        sh4[t] = s;
        __syncthreads();
        for (int o = 128; o > 0; o >>= 1) {
            if (t < o) {
                sh4[t].x += sh4[t + o].x; sh4[t].y += sh4[t + o].y;
                sh4[t].z += sh4[t + o].z; sh4[t].w += sh4[t + o].w;
            }
            __syncthreads();
        }
        if (t == 0) {
            float4 v = sh4[0];
            float l0 = v.x + gb[0], l1 = v.y + gb[1], l2 = v.z + gb[2], l3 = v.w + gb[3];
            float mx = fmaxf(fmaxf(l0, l1), fmaxf(l2, l3));
            float e0 = expf(l0 - mx), e1 = expf(l1 - mx), e2 = expf(l2 - mx), e3 = expf(l3 - mx);
            float inv = 1.f / (e0 + e1 + e2 + e3);
            *(float4*)&g_gate[bid * 4] = make_float4(e0 * inv, e1 * inv, e2 * inv, e3 * inv);
        }
    } else if (bid == N_) {
        int j = t >> 3, l = t & 7;
        float p = 0.f;
        for (int u = l; u < U_; u += 8) p += na[u] * W1[u * 32 + j];
        red[t] = p;
        __syncthreads();
        if (l == 0) {
            float s = 0.f;
            for (int q = 0; q < 8; q++) s += red[j * 8 + q];
            h32[j] = fmaxf(s + b1[j], 0.f);
        }
        __syncthreads();
        for (int u = t; u < U_; u += 256) {
            float s = b2[u];
            #pragma unroll
            for (int jj = 0; jj < 32; jj++) s += h32[jj] * W2[jj * U_ + u];
            g_cm[u] = mask[u] * sigmoidf_(s);
        }
    } else if (bid == N_ + 1) {
        if (t == 0) {
            float m = -1e30f;
            for (int i = 0; i < 9; i++) m = fmaxf(m, aw[i]);
            float e[9], s = 0.f;
            for (int i = 0; i < 9; i++) { e[i] = expf(aw[i] - m); s += e[i]; }
            float inv = 1.f / s;
            for (int i = 0; i < 8; i++) g_wts[i] = e[i] * inv;
        }
    } else {
        int bc = bid - (N_ + 2);
        int rc = bc >> 5, cc = bc & 31;
        int c = cc * 32 + (t & 31), ty = t >> 5;
        float s = 0.f;
        const float* p = mem + (size_t)(rc * 1024 + ty) * MD_ + c;
        #pragma unroll 4
        for (int i = 0; i < 128; i++) s += p[(size_t)i * 8 * MD_];
        red[t] = s;
        __syncthreads();
        if (ty == 0) {
            float tot = 0.f;
            #pragma unroll
            for (int q = 0; q < 8; q++) tot += red[q * 32 + (t & 31)];
            g_cmpart[rc * MD_ + c] = tot;
        }
    }
}

// ---------------- w * sigmoid(delay) -> bf16 ----------------
__global__ void k_wmod(const float4* __restrict__ w, const float4* __restrict__ delay) {
    int i = blockIdx.x * blockDim.x + threadIdx.x;   // 2M float4s
    float4 wv = w[i], dv = delay[i];
    __nv_bfloat162* o = (__nv_bfloat162*)g_wcb;
    o[i * 2 + 0] = __floats2bfloat162_rn(wv.x * sigmoidf_(dv.x), wv.y * sigmoidf_(dv.y));
    o[i * 2 + 1] = __floats2bfloat162_rn(wv.z * sigmoidf_(dv.z), wv.w * sigmoidf_(dv.w));
}

// ---------------- activation blend (a >= 0) ----------------
__device__ __forceinline__ float blendf(float a, const float* w) {
    const float SELU_SCALE = 1.0507009873554804934f;
    float e = __expf(-a);
    float sig = __fdividef(1.f, 1.f + e);
    float th = tanh_ap(a);
    float gelu = 0.5f * a * (1.f + erff(a * 0.70710678118654752440f));
    float sp = a + __logf(1.f + e);
    float mish = a * tanh_ap(sp);
    return w[0] * sig + w[2] * th + (w[1] + w[3] + SELU_SCALE * w[6]) * a
         + w[4] * a * sig + w[5] * gelu + w[7] * mish;
}

// ---------------- bf16 mma GEMM, BK=64 macro-chunks + appended glue CTAs -------------
// A [rows,KSTRIDE] bf16 row-major; B [K,NG] bf16 row-major (ldmatrix.trans).
// CTA tile 128x128, 4 warps, warp tile 64x64. Macro-chunk = K64 as two stacked
// 8KB sub-tiles per operand. Stage = 32KB; ring of 3 (96KB); one wait + two
// barriers per macro-chunk; 4-slice fragment ping-pong with cross-chunk prefetch.
// blockIdx.y >= 16: glue CTA -> grid-strided fp32->bf16 convert (gsrc->gdst), exit.
// blockIdx.z = K-slice (split-K for EPI 2).
template<int KLEN, int KSTRIDE, int NG, int EPI>
__global__ void __launch_bounds__(128, 2)
gemm_bf16(const __nv_bfloat16* __restrict__ Ag, const __nv_bfloat16* __restrict__ Bg,
          const float* __restrict__ bias, float* __restrict__ outp,
          const float4* __restrict__ gsrc, __nv_bfloat162* __restrict__ gdst,
          int gluef4) {
    constexpr int SUB   = 16384;        // [A 8KB][B 8KB]
    constexpr int STAGE = 32768;        // 2 sub-tiles
    constexpr int NCM   = KLEN / 64;

    // ---- appended glue CTAs: pure fp32 -> bf16 convert, then exit ----
    if (blockIdx.y >= 16) {
        int gcta = (blockIdx.y - 16) * gridDim.x + blockIdx.x;
        int nctas = (gridDim.y - 16) * gridDim.x;
        size_t stride = (size_t)nctas * 128;
        for (size_t i = (size_t)gcta * 128 + threadIdx.x; i < (size_t)gluef4; i += stride) {
            float4 v = gsrc[i];
            gdst[i * 2 + 0] = __floats2bfloat162_rn(v.x, v.y);
            gdst[i * 2 + 1] = __floats2bfloat162_rn(v.z, v.w);
        }
        return;
    }

    extern __shared__ char smem[];
    const uint32_t sb = smem_u32(smem);
    const int tid = threadIdx.x;
    const int lane = tid & 31, wid = tid >> 5;
    const int wm = wid & 1, wn = wid >> 1;
    const int lrow = lane >> 2, lcol = lane & 3;
    const int m0 = blockIdx.y * 128, n0 = blockIdx.x * 128;
    const int kz = blockIdx.z;

    float acc[4][8][4];
    #pragma unroll
    for (int i = 0; i < 4; i++)
        #pragma unroll
        for (int j = 0; j < 8; j++)
            #pragma unroll
            for (int q = 0; q < 4; q++) acc[i][j][q] = 0.f;

    // cp.async loop-invariant offsets (per sub-tile)
    const char* baseA = (const char*)(Ag + (size_t)m0 * KSTRIDE + (size_t)kz * KLEN);
    const char* baseB = (const char*)(Bg + n0 + (size_t)kz * KLEN * NG);
    uint32_t ago[4], asmo[4], bgo[4], bsmo[4];
    #pragma unroll
    for (int i = 0; i < 4; i++) {
        int id = tid + i * 128, r = id >> 2, j = id & 3;
        ago[i] = r * (KSTRIDE * 2) + j * 16;
        asmo[i] = r * 64 + ((j ^ ((r >> 1) & 3)) << 4);
    }
    #pragma unroll
    for (int i = 0; i < 4; i++) {
        int id = tid + i * 128, r = id >> 4, c = id & 15;
        bgo[i] = r * (NG * 2) + c * 16;
        bsmo[i] = r * 256 + ((c ^ (r & 7)) << 4);
    }

    // ldmatrix loop-invariant offsets (within one sub-tile)
    const int msel = lane >> 3;
    uint32_t aoff[4], boff[4];
    #pragma unroll
    for (int i = 0; i < 4; i++) {
        int row = wm * 64 + i * 16 + (msel & 1) * 8 + (lane & 7);
        int kc = msel >> 1;
        aoff[i] = row * 64 + ((kc ^ ((row >> 1) & 3)) << 4);
    }
    #pragma unroll
    for (int jg = 0; jg < 4; jg++) {
        int krow = (msel & 1) * 8 + (lane & 7);
        int c = wn * 8 + jg * 2 + (msel >> 1);
        boff[jg] = krow * 256 + ((c ^ (krow & 7)) << 4);
    }

    auto load_stage = [&](int slot) {
        #pragma unroll
        for (int t = 0; t < 2; t++) {
            uint32_t sA = sb + slot * STAGE + t * SUB, sB = sA + 8192;
            #pragma unroll
            for (int i = 0; i < 4; i++) cp16(sA + asmo[i], baseA + t * 64 + ago[i]);
            #pragma unroll
            for (int i = 0; i < 4; i++)
                cp16(sB + bsmo[i], baseB + (size_t)t * 32 * NG * 2 + bgo[i]);
        }
        cp_commit();
        baseA += 128;                       // 64 bf16 along K
        baseB += (size_t)64 * NG * 2;       // 64 k-rows
    };
    load_stage(0);
    load_stage(1);
    load_stage(2);

    uint32_t av0[4][4], bv0[8][2], av1[4][4], bv1[8][2];

    auto ld_slice_a = [&](uint32_t (&av)[4][4], uint32_t base, int half) {
        #pragma unroll
        for (int i = 0; i < 4; i++)
            ldsm4(av[i][0], av[i][1], av[i][2], av[i][3],
                  base + (half ? (aoff[i] ^ 0x20u) : aoff[i]));
    };
    auto ld_slice_b = [&](uint32_t (&bv)[8][2], uint32_t base, int half) {
        #pragma unroll
        for (int jg = 0; jg < 4; jg++) {
            uint32_t r0, r1, r2, r3;
            ldsm4t(r0, r1, r2, r3, base + 8192 + boff[jg] + half * 4096);
            bv[2 * jg][0] = r0;     bv[2 * jg][1] = r1;
            bv[2 * jg + 1][0] = r2; bv[2 * jg + 1][1] = r3;
        }
    };
    auto do_mma = [&](uint32_t (&av)[4][4], uint32_t (&bv)[8][2]) {
        #pragma unroll
        for (int i = 0; i < 4; i++)
            #pragma unroll
            for (int j = 0; j < 8; j++)
                mma_bf16(acc[i][j], av[i], bv[j]);
    };

    // preamble: stage 0 resident; load macro-chunk-0 slice-0 fragments
    cp_wait<2>();
    __syncthreads();
    ld_slice_a(av0, sb, 0);
    ld_slice_b(bv0, sb, 0);

    #pragma unroll 1
    for (int mc = 0; mc < NCM; mc++) {
        // stages mc and mc+1 resident
        if (mc + 3 <= NCM) cp_wait<1>(); else cp_wait<0>();
        __syncthreads();                                   // barrier 1
        uint32_t sA = sb + (mc % 3) * STAGE;

        ld_slice_a(av1, sA, 1);
        ld_slice_b(bv1, sA, 1);
        do_mma(av0, bv0);
        ld_slice_a(av0, sA + SUB, 0);
        ld_slice_b(bv0, sA + SUB, 0);
        do_mma(av1, bv1);
        ld_slice_a(av1, sA + SUB, 1);
        ld_slice_b(bv1, sA + SUB, 1);
        do_mma(av0, bv0);
        if (mc + 1 < NCM) {
            uint32_t sAn = sb + ((mc + 1) % 3) * STAGE;
            ld_slice_a(av0, sAn, 0);
            ld_slice_b(bv0, sAn, 0);
        }
        do_mma(av1, bv1);

        __syncthreads();                                   // barrier 2: slot mc%3 free
        if (mc + 3 < NCM) load_stage((mc + 3) % 3);        // stage mc+3 -> slot mc%3
    }

    // ---------------- epilogues ----------------
    if (EPI == 0) {
        float w[8];
        #pragma unroll
        for (int q = 0; q < 8; q++) w[q] = g_wts[q];
        const int cb = (lane & 1) * 2;
        #pragma unroll
        for (int i = 0; i < 4; i++) {
            int r0 = m0 + wm * 64 + i * 16 + lrow;
            int r1 = r0 + 8;
            float gA0 = g_gate[r0 * 4 + cb], gA1 = g_gate[r0 * 4 + cb + 1];
            float gB0 = g_gate[r1 * 4 + cb], gB1 = g_gate[r1 * 4 + cb + 1];
            #pragma unroll
            for (int j = 0; j < 8; j++) {
                int col0 = n0 + wn * 64 + j * 8 + 2 * lcol;
                float bb0 = bias[col0], bb1 = bias[col0 + 1];
                float pl = (acc[i][j][0] + bb0) * gA0 + (acc[i][j][1] + bb1) * gA1;
                float ph = (acc[i][j][2] + bb0) * gB0 + (acc[i][j][3] + bb1) * gB1;
                pl += __shfl_xor_sync(0xFFFFFFFFu, pl, 1);
                ph += __shfl_xor_sync(0xFFFFFFFFu, ph, 1);
                float z = (lane & 1) ? ph : pl;
                int row = (lane & 1) ? r1 : r0;
                int u = (n0 + wn * 64 + j * 8 + (lane & 2) * 2) >> 2;
                float a = fmaxf(z * g_cm[u], 0.f);
                g_blend[(size_t)row * U_ + u] = __float2bfloat16(blendf(a, w));
            }
        }
    } else if (EPI == 1) {
        // logits -> bf16
        #pragma unroll
        for (int i = 0; i < 4; i++) {
            int r0 = m0 + wm * 64 + i * 16 + lrow;
            int r1 = r0 + 8;
            #pragma unroll
            for (int j = 0; j < 8; j++) {
                int col0 = n0 + wn * 64 + j * 8 + 2 * lcol;
                float bb0 = bias[col0], bb1 = bias[col0 + 1];
                *(__nv_bfloat162*)&g_logits[(size_t)r0 * M_ + col0] =
                    __floats2bfloat162_rn(acc[i][j][0] + bb0, acc[i][j][1] + bb1);
                *(__nv_bfloat162*)&g_logits[(size_t)r1 * M_ + col0] =
                    __floats2bfloat162_rn(acc[i][j][2] + bb0, acc[i][j][3] + bb1);
            }
        }
    } else {
        // split-K partial write (fp32) into slice kz of the partial buffer
        float* part = outp + (size_t)kz * N_ * MD_;
        #pragma unroll
        for (int i = 0; i < 4; i++) {
            int r0 = m0 + wm * 64 + i * 16 + lrow;
            int r1 = r0 + 8;
            #pragma unroll
            for (int j = 0; j < 8; j++) {
                int col0 = n0 + wn * 64 + j * 8 + 2 * lcol;
                *(float2*)&part[(size_t)r0 * MD_ + col0] =
                    make_float2(acc[i][j][0], acc[i][j][1]);
                *(float2*)&part[(size_t)r1 * MD_ + col0] =
                    make_float2(acc[i][j][2], acc[i][j][3]);
            }
        }
    }
}

// ---------------- softmax: bf16 logits -> bf16 (attn - 1/M) ----------------
__global__ void __launch_bounds__(256) k_softmax() {
    __shared__ float sm[256];
    int n = blockIdx.x, t = threadIdx.x;
    const uint4* row4 = (const uint4*)&g_logits[(size_t)n * M_];   // 8 bf16 per uint4
    uint4 v[4];
    float f[32];
    #pragma unroll
    for (int i = 0; i < 4; i++) {
        v[i] = row4[t + i * 256];
        const __nv_bfloat162* h = (const __nv_bfloat162*)&v[i];
        #pragma unroll
        for (int q = 0; q < 4; q++) {
            float2 p = __bfloat1622float2(h[q]);
            f[i * 8 + q * 2] = p.x; f[i * 8 + q * 2 + 1] = p.y;
        }
    }
    float mx = -3.4e38f;
    #pragma unroll
    for (int q = 0; q < 32; q++) mx = fmaxf(mx, f[q]);
    sm[t] = mx; __syncthreads();
    for (int o = 128; o > 0; o >>= 1) {
        if (t < o) sm[t] = fmaxf(sm[t], sm[t + o]);
        __syncthreads();
    }
    mx = sm[0]; __syncthreads();
    float s = 0.f;
    #pragma unroll
    for (int q = 0; q < 32; q++) { f[q] = expf(f[q] - mx); s += f[q]; }
    sm[t] = s; __syncthreads();
    for (int o = 128; o > 0; o >>= 1) {
        if (t < o) sm[t] += sm[t + o];
        __syncthreads();
    }
    float inv = 1.f / sm[0];
    const float im = 1.f / (float)M_;
    uint4* dst = (uint4*)&g_attnd[(size_t)n * M_];
    #pragma unroll
    for (int i = 0; i < 4; i++) {
        uint4 o;
        __nv_bfloat162* h = (__nv_bfloat162*)&o;
        #pragma unroll
        for (int q = 0; q < 4; q++)
            h[q] = __floats2bfloat162_rn(f[i * 8 + q * 2] * inv - im,
                                         f[i * 8 + q * 2 + 1] * inv - im);
        dst[t + i * 256] = o;
    }
}

// ---------------- reduce: out = part0 + part1 + colmean ----------------
__global__ void __launch_bounds__(256) k_red(const float* __restrict__ part,
                                             float* __restrict__ out) {
    int t = threadIdx.x;
    int c0 = t * 4;
    float cm[4];
    #pragma unroll
    for (int q = 0; q < 4; q++) {
        float s = 0.f;
        #pragma unroll
        for (int p = 0; p < 8; p++) s += g_cmpart[p * MD_ + c0 + q];
        cm[q] = s * (1.f / (float)M_);
    }
    const float4* p0 = (const float4*)part;
    const float4* p1 = p0 + ((size_t)N_ * MD_ / 4);
    float4* o4 = (float4*)out;
    int rbase = blockIdx.x * 16;
    #pragma unroll
    for (int r = 0; r < 16; r++) {
        size_t idx = (size_t)(rbase + r) * (MD_ / 4) + t;
        float4 a = p0[idx], b = p1[idx];
        o4[idx] = make_float4(a.x + b.x + cm[0], a.y + b.y + cm[1],
                              a.z + b.z + cm[2], a.w + b.w + cm[3]);
    }
}

// ---------------- launch ----------------
extern "C" void kernel_launch(void* const* d_in, const int* in_sizes, int n_in,
                              void* d_out, int out_size) {
    const float* x        = (const float*)d_in[0];
    const float* w        = (const float*)d_in[1];
    const float* delay    = (const float*)d_in[2];
    const float* b        = (const float*)d_in[3];
    const float* gate_W   = (const float*)d_in[4];
    const float* gate_b   = (const float*)d_in[5];
    const float* navg     = (const float*)d_in[6];
    const float* conn_W1  = (const float*)d_in[7];
    const float* conn_b1  = (const float*)d_in[8];
    const float* conn_W2  = (const float*)d_in[9];
    const float* conn_b2  = (const float*)d_in[10];
    const float* mask     = (const float*)d_in[11];
    const float* act_w    = (const float*)d_in[12];
    const float* read_W   = (const float*)d_in[13];
    const float* read_b   = (const float*)d_in[14];
    const float* memory   = (const float*)d_in[15];
    float* out = (float*)d_out;

    __nv_bfloat16 *p_xbf, *p_wcb, *p_rwb, *p_memb, *p_blend, *p_attnd, *p_logits;
    cudaGetSymbolAddress((void**)&p_xbf, g_xbf);
    cudaGetSymbolAddress((void**)&p_wcb, g_wcb);
    cudaGetSymbolAddress((void**)&p_rwb, g_rwb);
    cudaGetSymbolAddress((void**)&p_memb, g_memb);
    cudaGetSymbolAddress((void**)&p_blend, g_blend);
    cudaGetSymbolAddress((void**)&p_attnd, g_attnd);
    cudaGetSymbolAddress((void**)&p_logits, g_logits);
    float* p_part = (float*)p_logits;   // reuse logits storage for GEMM3 partials

    cudaFuncSetAttribute(gemm_bf16<D_, D_, U_ * NB_, 0>,
                         cudaFuncAttributeMaxDynamicSharedMemorySize, 98304);
    cudaFuncSetAttribute(gemm_bf16<U_, U_, M_, 1>,
                         cudaFuncAttributeMaxDynamicSharedMemorySize, 98304);
    cudaFuncSetAttribute(gemm_bf16<M_ / 2, M_, MD_, 2>,
                         cudaFuncAttributeMaxDynamicSharedMemorySize, 98304);

    // 1: misc (gate + x->bf16 / conn / actw / colsums)
    k_misc<<<N_ + 2 + 256, 256>>>(x, gate_W, gate_b, navg, conn_W1, conn_b1,
                                  conn_W2, conn_b2, mask, act_w, memory);
    // 2: w * sigmoid(delay) -> bf16
    k_wmod<<<8192, 256>>>((const float4*)w, (const float4*)delay);
    // 3: GEMM1 (profiled slot) + appended glue: read_W -> bf16 (for GEMM2)
    gemm_bf16<D_, D_, U_ * NB_, 0><<<dim3(64, 20, 1), 128, 98304>>>(
        p_xbf, p_wcb, b, nullptr,
        (const float4*)read_W, (__nv_bfloat162*)p_rwb, (int)((size_t)U_ * M_ / 4));
    // 4: GEMM2 -> bf16 logits + appended glue: memory -> bf16 (for GEMM3)
    gemm_bf16<U_, U_, M_, 1><<<dim3(64, 18, 1), 128, 98304>>>(
        p_blend, p_rwb, read_b, nullptr,
        (const float4*)memory, (__nv_bfloat162*)p_memb, (int)((size_t)M_ * MD_ / 4));
    // 5: softmax -> attnd (bf16)
    k_softmax<<<N_, 256>>>();
    // 6: GEMM3 split-K=2 -> fp32 partials
    gemm_bf16<M_ / 2, M_, MD_, 2><<<dim3(8, 16, 2), 128, 98304>>>(
        p_attnd, p_memb, nullptr, p_part, nullptr, nullptr, 0);
    // 7: reduce partials + colmean -> out
    k_red<<<128, 256>>>(p_part, out);
}

// round 15
// speedup vs baseline: 1.2351x; 1.2351x over previous
#include <cuda_runtime.h>
#include <cuda_bf16.h>
#include <math.h>
#include <stdint.h>

#define N_  2048
#define D_  1024
#define U_  2048
#define NB_ 4
#define M_  8192
#define MD_ 1024

// ---------------- scratch (device globals; no allocs allowed) ----------------
__device__ __align__(16) __nv_bfloat16 g_xbf[(size_t)N_ * D_];        // x bf16 [N,D]
__device__ __align__(16) __nv_bfloat16 g_wcb[(size_t)D_ * U_ * NB_];  // w*sig(delay) bf16 [D,8192]
__device__ __align__(16) __nv_bfloat16 g_rwb[(size_t)U_ * M_];        // read_W bf16 [U,M]
__device__ __align__(16) __nv_bfloat16 g_memb[(size_t)M_ * MD_];      // memory bf16 [M,MD]
__device__ __align__(16) __nv_bfloat16 g_blend[(size_t)N_ * U_];      // bf16 [N,U]
__device__ __align__(16) __nv_bfloat16 g_logits[(size_t)N_ * M_];     // bf16 logits; later
                                                                      // reused as 2x fp32 GEMM3 partials
__device__ __align__(16) __nv_bfloat16 g_attnd[(size_t)N_ * M_];      // (attn-1/M) bf16
__device__ float g_cmpart[8 * MD_];                                   // colsum partials
__device__ float g_gate[N_ * NB_];
__device__ float g_cm[U_];
__device__ float g_wts[8];

// ---------------- PTX helpers ----------------
__device__ __forceinline__ uint32_t smem_u32(const void* p) {
    uint32_t a;
    asm("{ .reg .u64 t; cvta.to.shared.u64 t, %1; cvt.u32.u64 %0, t; }" : "=r"(a) : "l"(p));
    return a;
}
__device__ __forceinline__ void cp16(uint32_t s, const void* g) {
    asm volatile("cp.async.cg.shared.global [%0], [%1], 16;" :: "r"(s), "l"(g));
}
__device__ __forceinline__ void cp_commit() { asm volatile("cp.async.commit_group;"); }
template<int NN> __device__ __forceinline__ void cp_wait() {
    asm volatile("cp.async.wait_group %0;" :: "n"(NN));
}
__device__ __forceinline__ void ldsm4(uint32_t& r0, uint32_t& r1, uint32_t& r2, uint32_t& r3,
                                      uint32_t a) {
    asm volatile("ldmatrix.sync.aligned.m8n8.x4.shared.b16 {%0,%1,%2,%3}, [%4];"
                 : "=r"(r0), "=r"(r1), "=r"(r2), "=r"(r3) : "r"(a));
}
__device__ __forceinline__ void ldsm4t(uint32_t& r0, uint32_t& r1, uint32_t& r2, uint32_t& r3,
                                       uint32_t a) {
    asm volatile("ldmatrix.sync.aligned.m8n8.x4.trans.shared.b16 {%0,%1,%2,%3}, [%4];"
                 : "=r"(r0), "=r"(r1), "=r"(r2), "=r"(r3) : "r"(a));
}
__device__ __forceinline__ void mma_bf16(float* c, const uint32_t* a, const uint32_t* b) {
    asm volatile(
        "mma.sync.aligned.m16n8k16.row.col.f32.bf16.bf16.f32 "
        "{%0,%1,%2,%3}, {%4,%5,%6,%7}, {%8,%9}, {%0,%1,%2,%3};"
        : "+f"(c[0]), "+f"(c[1]), "+f"(c[2]), "+f"(c[3])
        : "r"(a[0]), "r"(a[1]), "r"(a[2]), "r"(a[3]), "r"(b[0]), "r"(b[1]));
}
__device__ __forceinline__ float sigmoidf_(float x) { return 1.f / (1.f + expf(-x)); }
__device__ __forceinline__ float tanh_ap(float x) {
    float r;
    asm("tanh.approx.f32 %0, %1;" : "=f"(r) : "f"(x));
    return r;
}

// ---------------- k_misc: gate softmax (+x->bf16) + conn + act weights + colsums ------
__global__ void __launch_bounds__(256) k_misc(
    const float* __restrict__ x, const float* __restrict__ gW, const float* __restrict__ gb,
    const float* __restrict__ na, const float* __restrict__ W1, const float* __restrict__ b1,
    const float* __restrict__ W2, const float* __restrict__ b2, const float* __restrict__ mask,
    const float* __restrict__ aw, const float* __restrict__ mem) {
    __shared__ float4 sh4[256];
    __shared__ float red[256];
    __shared__ float h32[32];
    int bid = blockIdx.x, t = threadIdx.x;
    if (bid < N_) {
        float4 s = make_float4(0.f, 0.f, 0.f, 0.f);
        #pragma unroll
        for (int i = 0; i < 4; i++) {
            int d = t + i * 256;
            float xv = x[bid * D_ + d];
            g_xbf[(size_t)bid * D_ + d] = __float2bfloat16(xv);   // fused x -> bf16
            float4 g = *(const float4*)&gW[d * 4];
            s.x += xv * g.x; s.y += xv * g.y; s.z += xv * g.z; s.w += xv * g.w;
        }
        sh4[t] = s;
        __syncthreads();
        for (int o = 128; o > 0; o >>= 1) {
            if (t < o) {
                sh4[t].x += sh4[t + o].x; sh4[t].y += sh4[t + o].y;
                sh4[t].z += sh4[t + o].z; sh4[t].w += sh4[t + o].w;
            }
            __syncthreads();
        }
        if (t == 0) {
            float4 v = sh4[0];
            float l0 = v.x + gb[0], l1 = v.y + gb[1], l2 = v.z + gb[2], l3 = v.w + gb[3];
            float mx = fmaxf(fmaxf(l0, l1), fmaxf(l2, l3));
            float e0 = expf(l0 - mx), e1 = expf(l1 - mx), e2 = expf(l2 - mx), e3 = expf(l3 - mx);
            float inv = 1.f / (e0 + e1 + e2 + e3);
            *(float4*)&g_gate[bid * 4] = make_float4(e0 * inv, e1 * inv, e2 * inv, e3 * inv);
        }
    } else if (bid == N_) {
        int j = t >> 3, l = t & 7;
        float p = 0.f;
        for (int u = l; u < U_; u += 8) p += na[u] * W1[u * 32 + j];
        red[t] = p;
        __syncthreads();
        if (l == 0) {
            float s = 0.f;
            for (int q = 0; q < 8; q++) s += red[j * 8 + q];
            h32[j] = fmaxf(s + b1[j], 0.f);
        }
        __syncthreads();
        for (int u = t; u < U_; u += 256) {
            float s = b2[u];
            #pragma unroll
            for (int jj = 0; jj < 32; jj++) s += h32[jj] * W2[jj * U_ + u];
            g_cm[u] = mask[u] * sigmoidf_(s);
        }
    } else if (bid == N_ + 1) {
        if (t == 0) {
            float m = -1e30f;
            for (int i = 0; i < 9; i++) m = fmaxf(m, aw[i]);
            float e[9], s = 0.f;
            for (int i = 0; i < 9; i++) { e[i] = expf(aw[i] - m); s += e[i]; }
            float inv = 1.f / s;
            for (int i = 0; i < 8; i++) g_wts[i] = e[i] * inv;
        }
    } else {
        int bc = bid - (N_ + 2);
        int rc = bc >> 5, cc = bc & 31;
        int c = cc * 32 + (t & 31), ty = t >> 5;
        float s = 0.f;
        const float* p = mem + (size_t)(rc * 1024 + ty) * MD_ + c;
        #pragma unroll 4
        for (int i = 0; i < 128; i++) s += p[(size_t)i * 8 * MD_];
        red[t] = s;
        __syncthreads();
        if (ty == 0) {
            float tot = 0.f;
            #pragma unroll
            for (int q = 0; q < 8; q++) tot += red[q * 32 + (t & 31)];
            g_cmpart[rc * MD_ + c] = tot;
        }
    }
}

// ---------------- elementwise fp32 -> bf16 ----------------
__global__ void k_cvt(const float4* __restrict__ src, __nv_bfloat162* __restrict__ dst) {
    int i = blockIdx.x * blockDim.x + threadIdx.x;
    float4 v = src[i];
    dst[i * 2 + 0] = __floats2bfloat162_rn(v.x, v.y);
    dst[i * 2 + 1] = __floats2bfloat162_rn(v.z, v.w);
}

// ---------------- w * sigmoid(delay) -> bf16 ----------------
__global__ void k_wmod(const float4* __restrict__ w, const float4* __restrict__ delay) {
    int i = blockIdx.x * blockDim.x + threadIdx.x;   // 2M float4s
    float4 wv = w[i], dv = delay[i];
    __nv_bfloat162* o = (__nv_bfloat162*)g_wcb;
    o[i * 2 + 0] = __floats2bfloat162_rn(wv.x * sigmoidf_(dv.x), wv.y * sigmoidf_(dv.y));
    o[i * 2 + 1] = __floats2bfloat162_rn(wv.z * sigmoidf_(dv.z), wv.w * sigmoidf_(dv.w));
}

// ---------------- activation blend (a >= 0) ----------------
__device__ __forceinline__ float blendf(float a, const float* w) {
    const float SELU_SCALE = 1.0507009873554804934f;
    float e = __expf(-a);
    float sig = __fdividef(1.f, 1.f + e);
    float th = tanh_ap(a);
    float gelu = 0.5f * a * (1.f + erff(a * 0.70710678118654752440f));
    float sp = a + __logf(1.f + e);
    float mish = a * tanh_ap(sp);
    return w[0] * sig + w[2] * th + (w[1] + w[3] + SELU_SCALE * w[6]) * a
         + w[4] * a * sig + w[5] * gelu + w[7] * mish;
}

// ---------------- bf16 mma GEMM, BK=64 macro-chunks ----------------
// A [rows,KSTRIDE] bf16 row-major; B [K,NG] bf16 row-major (ldmatrix.trans).
// CTA tile 128x128, 4 warps, warp tile 64x64. Macro-chunk = K64 as two stacked
// 8KB sub-tiles per operand. Stage = 32KB; ring of 3 slots (96KB); one wait +
// two barriers per macro-chunk; 4-slice fragment ping-pong with cross-chunk
// prefetch. blockIdx.z = K-slice (split-K for EPI 2).
template<int KLEN, int KSTRIDE, int NG, int EPI>
__global__ void __launch_bounds__(128, 2)
gemm_bf16(const __nv_bfloat16* __restrict__ Ag, const __nv_bfloat16* __restrict__ Bg,
          const float* __restrict__ bias, float* __restrict__ outp) {
    constexpr int SUB   = 16384;        // [A 8KB][B 8KB]
    constexpr int STAGE = 32768;        // 2 sub-tiles
    constexpr int NCM   = KLEN / 64;

    extern __shared__ char smem[];
    const uint32_t sb = smem_u32(smem);
    const int tid = threadIdx.x;
    const int lane = tid & 31, wid = tid >> 5;
    const int wm = wid & 1, wn = wid >> 1;
    const int lrow = lane >> 2, lcol = lane & 3;
    const int m0 = blockIdx.y * 128, n0 = blockIdx.x * 128;
    const int kz = blockIdx.z;

    float acc[4][8][4];
    #pragma unroll
    for (int i = 0; i < 4; i++)
        #pragma unroll
        for (int j = 0; j < 8; j++)
            #pragma unroll
            for (int q = 0; q < 4; q++) acc[i][j][q] = 0.f;

    // cp.async loop-invariant offsets (per sub-tile)
    const char* baseA = (const char*)(Ag + (size_t)m0 * KSTRIDE + (size_t)kz * KLEN);
    const char* baseB = (const char*)(Bg + n0 + (size_t)kz * KLEN * NG);
    uint32_t ago[4], asmo[4], bgo[4], bsmo[4];
    #pragma unroll
    for (int i = 0; i < 4; i++) {
        int id = tid + i * 128, r = id >> 2, j = id & 3;
        ago[i] = r * (KSTRIDE * 2) + j * 16;
        asmo[i] = r * 64 + ((j ^ ((r >> 1) & 3)) << 4);
    }
    #pragma unroll
    for (int i = 0; i < 4; i++) {
        int id = tid + i * 128, r = id >> 4, c = id & 15;
        bgo[i] = r * (NG * 2) + c * 16;
        bsmo[i] = r * 256 + ((c ^ (r & 7)) << 4);
    }

    // ldmatrix loop-invariant offsets (within one sub-tile)
    const int msel = lane >> 3;
    uint32_t aoff[4], boff[4];
    #pragma unroll
    for (int i = 0; i < 4; i++) {
        int row = wm * 64 + i * 16 + (msel & 1) * 8 + (lane & 7);
        int kc = msel >> 1;
        aoff[i] = row * 64 + ((kc ^ ((row >> 1) & 3)) << 4);
    }
    #pragma unroll
    for (int jg = 0; jg < 4; jg++) {
        int krow = (msel & 1) * 8 + (lane & 7);
        int c = wn * 8 + jg * 2 + (msel >> 1);
        boff[jg] = krow * 256 + ((c ^ (krow & 7)) << 4);
    }

    auto load_stage = [&](int slot) {
        #pragma unroll
        for (int t = 0; t < 2; t++) {
            uint32_t sA = sb + slot * STAGE + t * SUB, sB = sA + 8192;
            #pragma unroll
            for (int i = 0; i < 4; i++) cp16(sA + asmo[i], baseA + t * 64 + ago[i]);
            #pragma unroll
            for (int i = 0; i < 4; i++)
                cp16(sB + bsmo[i], baseB + (size_t)t * 32 * NG * 2 + bgo[i]);
        }
        cp_commit();
        baseA += 128;                       // 64 bf16 along K
        baseB += (size_t)64 * NG * 2;       // 64 k-rows
    };
    load_stage(0);
    load_stage(1);
    load_stage(2);

    uint32_t av0[4][4], bv0[8][2], av1[4][4], bv1[8][2];

    auto ld_slice_a = [&](uint32_t (&av)[4][4], uint32_t base, int half) {
        #pragma unroll
        for (int i = 0; i < 4; i++)
            ldsm4(av[i][0], av[i][1], av[i][2], av[i][3],
                  base + (half ? (aoff[i] ^ 0x20u) : aoff[i]));
    };
    auto ld_slice_b = [&](uint32_t (&bv)[8][2], uint32_t base, int half) {
        #pragma unroll
        for (int jg = 0; jg < 4; jg++) {
            uint32_t r0, r1, r2, r3;
            ldsm4t(r0, r1, r2, r3, base + 8192 + boff[jg] + half * 4096);
            bv[2 * jg][0] = r0;     bv[2 * jg][1] = r1;
            bv[2 * jg + 1][0] = r2; bv[2 * jg + 1][1] = r3;
        }
    };
    auto do_mma = [&](uint32_t (&av)[4][4], uint32_t (&bv)[8][2]) {
        #pragma unroll
        for (int i = 0; i < 4; i++)
            #pragma unroll
            for (int j = 0; j < 8; j++)
                mma_bf16(acc[i][j], av[i], bv[j]);
    };

    // preamble: stage 0 resident; load macro-chunk-0 slice-0 fragments
    cp_wait<2>();
    __syncthreads();
    ld_slice_a(av0, sb, 0);
    ld_slice_b(bv0, sb, 0);

    #pragma unroll 1
    for (int mc = 0; mc < NCM; mc++) {
        // stages mc and mc+1 resident
        if (mc + 3 <= NCM) cp_wait<1>(); else cp_wait<0>();
        __syncthreads();                                   // barrier 1
        uint32_t sA = sb + (mc % 3) * STAGE;

        ld_slice_a(av1, sA, 1);
        ld_slice_b(bv1, sA, 1);
        do_mma(av0, bv0);
        ld_slice_a(av0, sA + SUB, 0);
        ld_slice_b(bv0, sA + SUB, 0);
        do_mma(av1, bv1);
        ld_slice_a(av1, sA + SUB, 1);
        ld_slice_b(bv1, sA + SUB, 1);
        do_mma(av0, bv0);
        if (mc + 1 < NCM) {
            uint32_t sAn = sb + ((mc + 1) % 3) * STAGE;
            ld_slice_a(av0, sAn, 0);
            ld_slice_b(bv0, sAn, 0);
        }
        do_mma(av1, bv1);

        __syncthreads();                                   // barrier 2: slot mc%3 free
        if (mc + 3 < NCM) load_stage((mc + 3) % 3);        // stage mc+3 -> slot mc%3
    }

    // ---------------- epilogues ----------------
    if (EPI == 0) {
        float w[8];
        #pragma unroll
        for (int q = 0; q < 8; q++) w[q] = g_wts[q];
        const int cb = (lane & 1) * 2;
        #pragma unroll
        for (int i = 0; i < 4; i++) {
            int r0 = m0 + wm * 64 + i * 16 + lrow;
            int r1 = r0 + 8;
            float gA0 = g_gate[r0 * 4 + cb], gA1 = g_gate[r0 * 4 + cb + 1];
            float gB0 = g_gate[r1 * 4 + cb], gB1 = g_gate[r1 * 4 + cb + 1];
            #pragma unroll
            for (int j = 0; j < 8; j++) {
                int col0 = n0 + wn * 64 + j * 8 + 2 * lcol;
                float bb0 = bias[col0], bb1 = bias[col0 + 1];
                float pl = (acc[i][j][0] + bb0) * gA0 + (acc[i][j][1] + bb1) * gA1;
                float ph = (acc[i][j][2] + bb0) * gB0 + (acc[i][j][3] + bb1) * gB1;
                pl += __shfl_xor_sync(0xFFFFFFFFu, pl, 1);
                ph += __shfl_xor_sync(0xFFFFFFFFu, ph, 1);
                float z = (lane & 1) ? ph : pl;
                int row = (lane & 1) ? r1 : r0;
                int u = (n0 + wn * 64 + j * 8 + (lane & 2) * 2) >> 2;
                float a = fmaxf(z * g_cm[u], 0.f);
                g_blend[(size_t)row * U_ + u] = __float2bfloat16(blendf(a, w));
            }
        }
    } else if (EPI == 1) {
        // logits -> bf16
        #pragma unroll
        for (int i = 0; i < 4; i++) {
            int r0 = m0 + wm * 64 + i * 16 + lrow;
            int r1 = r0 + 8;
            #pragma unroll
            for (int j = 0; j < 8; j++) {
                int col0 = n0 + wn * 64 + j * 8 + 2 * lcol;
                float bb0 = bias[col0], bb1 = bias[col0 + 1];
                *(__nv_bfloat162*)&g_logits[(size_t)r0 * M_ + col0] =
                    __floats2bfloat162_rn(acc[i][j][0] + bb0, acc[i][j][1] + bb1);
                *(__nv_bfloat162*)&g_logits[(size_t)r1 * M_ + col0] =
                    __floats2bfloat162_rn(acc[i][j][2] + bb0, acc[i][j][3] + bb1);
            }
        }
    } else {
        // split-K partial write (fp32) into slice kz of the partial buffer
        float* part = outp + (size_t)kz * N_ * MD_;
        #pragma unroll
        for (int i = 0; i < 4; i++) {
            int r0 = m0 + wm * 64 + i * 16 + lrow;
            int r1 = r0 + 8;
            #pragma unroll
            for (int j = 0; j < 8; j++) {
                int col0 = n0 + wn * 64 + j * 8 + 2 * lcol;
                *(float2*)&part[(size_t)r0 * MD_ + col0] =
                    make_float2(acc[i][j][0], acc[i][j][1]);
                *(float2*)&part[(size_t)r1 * MD_ + col0] =
                    make_float2(acc[i][j][2], acc[i][j][3]);
            }
        }
    }
}

// ---------------- softmax: bf16 logits -> bf16 (attn - 1/M) ----------------
__global__ void __launch_bounds__(256) k_softmax() {
    __shared__ float sm[256];
    int n = blockIdx.x, t = threadIdx.x;
    const uint4* row4 = (const uint4*)&g_logits[(size_t)n * M_];   // 8 bf16 per uint4
    uint4 v[4];
    float f[32];
    #pragma unroll
    for (int i = 0; i < 4; i++) {
        v[i] = row4[t + i * 256];
        const __nv_bfloat162* h = (const __nv_bfloat162*)&v[i];
        #pragma unroll
        for (int q = 0; q < 4; q++) {
            float2 p = __bfloat1622float2(h[q]);
            f[i * 8 + q * 2] = p.x; f[i * 8 + q * 2 + 1] = p.y;
        }
    }
    float mx = -3.4e38f;
    #pragma unroll
    for (int q = 0; q < 32; q++) mx = fmaxf(mx, f[q]);
    sm[t] = mx; __syncthreads();
    for (int o = 128; o > 0; o >>= 1) {
        if (t < o) sm[t] = fmaxf(sm[t], sm[t + o]);
        __syncthreads();
    }
    mx = sm[0]; __syncthreads();
    float s = 0.f;
    #pragma unroll
    for (int q = 0; q < 32; q++) { f[q] = expf(f[q] - mx); s += f[q]; }
    sm[t] = s; __syncthreads();
    for (int o = 128; o > 0; o >>= 1) {
        if (t < o) sm[t] += sm[t + o];
        __syncthreads();
    }
    float inv = 1.f / sm[0];
    const float im = 1.f / (float)M_;
    uint4* dst = (uint4*)&g_attnd[(size_t)n * M_];
    #pragma unroll
    for (int i = 0; i < 4; i++) {
        uint4 o;
        __nv_bfloat162* h = (__nv_bfloat162*)&o;
        #pragma unroll
        for (int q = 0; q < 4; q++)
            h[q] = __floats2bfloat162_rn(f[i * 8 + q * 2] * inv - im,
                                         f[i * 8 + q * 2 + 1] * inv - im);
        dst[t + i * 256] = o;
    }
}

// ---------------- reduce: out = part0 + part1 + colmean ----------------
__global__ void __launch_bounds__(256) k_red(const float* __restrict__ part,
                                             float* __restrict__ out) {
    int t = threadIdx.x;
    int c0 = t * 4;
    float cm[4];
    #pragma unroll
    for (int q = 0; q < 4; q++) {
        float s = 0.f;
        #pragma unroll
        for (int p = 0; p < 8; p++) s += g_cmpart[p * MD_ + c0 + q];
        cm[q] = s * (1.f / (float)M_);
    }
    const float4* p0 = (const float4*)part;
    const float4* p1 = p0 + ((size_t)N_ * MD_ / 4);
    float4* o4 = (float4*)out;
    int rbase = blockIdx.x * 16;
    #pragma unroll
    for (int r = 0; r < 16; r++) {
        size_t idx = (size_t)(rbase + r) * (MD_ / 4) + t;
        float4 a = p0[idx], b = p1[idx];
        o4[idx] = make_float4(a.x + b.x + cm[0], a.y + b.y + cm[1],
                              a.z + b.z + cm[2], a.w + b.w + cm[3]);
    }
}

// ---------------- launch ----------------
extern "C" void kernel_launch(void* const* d_in, const int* in_sizes, int n_in,
                              void* d_out, int out_size) {
    const float* x        = (const float*)d_in[0];
    const float* w        = (const float*)d_in[1];
    const float* delay    = (const float*)d_in[2];
    const float* b        = (const float*)d_in[3];
    const float* gate_W   = (const float*)d_in[4];
    const float* gate_b   = (const float*)d_in[5];
    const float* navg     = (const float*)d_in[6];
    const float* conn_W1  = (const float*)d_in[7];
    const float* conn_b1  = (const float*)d_in[8];
    const float* conn_W2  = (const float*)d_in[9];
    const float* conn_b2  = (const float*)d_in[10];
    const float* mask     = (const float*)d_in[11];
    const float* act_w    = (const float*)d_in[12];
    const float* read_W   = (const float*)d_in[13];
    const float* read_b   = (const float*)d_in[14];
    const float* memory   = (const float*)d_in[15];
    float* out = (float*)d_out;

    __nv_bfloat16 *p_xbf, *p_wcb, *p_rwb, *p_memb, *p_blend, *p_attnd, *p_logits;
    cudaGetSymbolAddress((void**)&p_xbf, g_xbf);
    cudaGetSymbolAddress((void**)&p_wcb, g_wcb);
    cudaGetSymbolAddress((void**)&p_rwb, g_rwb);
    cudaGetSymbolAddress((void**)&p_memb, g_memb);
    cudaGetSymbolAddress((void**)&p_blend, g_blend);
    cudaGetSymbolAddress((void**)&p_attnd, g_attnd);
    cudaGetSymbolAddress((void**)&p_logits, g_logits);
    float* p_part = (float*)p_logits;   // reuse logits storage for GEMM3 partials

    cudaFuncSetAttribute(gemm_bf16<D_, D_, U_ * NB_, 0>,
                         cudaFuncAttributeMaxDynamicSharedMemorySize, 98304);
    cudaFuncSetAttribute(gemm_bf16<U_, U_, M_, 1>,
                         cudaFuncAttributeMaxDynamicSharedMemorySize, 98304);
    cudaFuncSetAttribute(gemm_bf16<M_ / 2, M_, MD_, 2>,
                         cudaFuncAttributeMaxDynamicSharedMemorySize, 98304);

    // side streams + events for graph-captured fork/join (created once; no device allocs)
    static cudaStream_t s1 = nullptr, s2 = nullptr;
    static cudaEvent_t evr = nullptr, evw = nullptr, evc = nullptr;
    if (s1 == nullptr) {
        cudaStreamCreateWithFlags(&s1, cudaStreamNonBlocking);
        cudaStreamCreateWithFlags(&s2, cudaStreamNonBlocking);
        cudaEventCreateWithFlags(&evr, cudaEventDisableTiming);
        cudaEventCreateWithFlags(&evw, cudaEventDisableTiming);
        cudaEventCreateWithFlags(&evc, cudaEventDisableTiming);
    }

    // fork
    cudaEventRecord(evr, 0);
    cudaStreamWaitEvent(s1, evr, 0);
    cudaStreamWaitEvent(s2, evr, 0);

    // s1: w * sigmoid(delay) -> bf16   (needed by GEMM1)
    k_wmod<<<8192, 256, 0, s1>>>((const float4*)w, (const float4*)delay);
    cudaEventRecord(evw, s1);

    // s2: read_W -> bf16, memory -> bf16   (needed by GEMM2 / GEMM3)
    k_cvt<<<16384, 256, 0, s2>>>((const float4*)read_W, (__nv_bfloat162*)p_rwb);
    k_cvt<<<8192, 256, 0, s2>>>((const float4*)memory, (__nv_bfloat162*)p_memb);
    cudaEventRecord(evc, s2);

    // default: misc (gate + x->bf16 / conn / actw / colsums), parallel with s1/s2
    k_misc<<<N_ + 2 + 256, 256>>>(x, gate_W, gate_b, navg, conn_W1, conn_b1,
                                  conn_W2, conn_b2, mask, act_w, memory);

    // join wmod, then GEMM1 (cvts on s2 still overlap GEMM1)
    cudaStreamWaitEvent(0, evw, 0);
    gemm_bf16<D_, D_, U_ * NB_, 0><<<dim3(64, 16, 1), 128, 98304>>>(p_xbf, p_wcb, b, nullptr);

    // join cvts, then GEMM2 -> bf16 logits
    cudaStreamWaitEvent(0, evc, 0);
    gemm_bf16<U_, U_, M_, 1><<<dim3(64, 16, 1), 128, 98304>>>(p_blend, p_rwb, read_b, nullptr);

    // softmax -> attnd (bf16)
    k_softmax<<<N_, 256>>>();
    // GEMM3 split-K=2 -> fp32 partials
    gemm_bf16<M_ / 2, M_, MD_, 2><<<dim3(8, 16, 2), 128, 98304>>>(p_attnd, p_memb,
                                                                  nullptr, p_part);
    // reduce partials + colmean -> out
    k_red<<<128, 256>>>(p_part, out);
}